// round 1
// baseline (speedup 1.0000x reference)
#include <cuda_runtime.h>
#include <math.h>

#define B 512
#define D 512
#define C 1000
#define M 200
#define KP 50
#define KN 20
#define NROWS (C*KN)              // 20000
#define TEMP 0.07f
#define MARGIN 0.5f
#define BM 64
#define BN 128
#define BK 16
#define NT ((NROWS + BN - 1)/BN)  // 157

// ---------------- scratch (static device globals; no allocation) ----------------
__device__ float g_f[B*D];        // normalized features
__device__ int   g_rank[B];
__device__ int   g_gsize[B];
__device__ int   g_fidx[B];
__device__ int   g_ov[C*KP];      // override: batch index written into mem[c][k], else -1
__device__ float g_own[B];
__device__ float g_posb[B];
__device__ int   g_cntb[B];
__device__ float g_all [NT*B];    // per-(ntile, b) partials (deterministic reduction)
__device__ float g_hard[NT*B];
__device__ int   g_hcnt[NT*B];

// ---------------- init override table ----------------
__global__ void k_init() {
    int i = blockIdx.x * blockDim.x + threadIdx.x;
    if (i < C*KP) g_ov[i] = -1;
}

// ---------------- L2 normalize rows of features ----------------
__global__ void k_norm(const float* __restrict__ x) {
    int r = blockIdx.x, t = threadIdx.x;
    __shared__ float red[8];
    __shared__ float inv_s;
    const float* row = x + (size_t)r * D;
    float s = 0.f;
    for (int d = t; d < D; d += 256) { float v = row[d]; s = fmaf(v, v, s); }
    for (int o = 16; o; o >>= 1) s += __shfl_down_sync(0xffffffffu, s, o);
    if ((t & 31) == 0) red[t >> 5] = s;
    __syncthreads();
    if (t == 0) {
        float tot = 0.f;
        for (int i = 0; i < 8; i++) tot += red[i];
        inv_s = 1.0f / fmaxf(sqrtf(tot), 1e-12f);
    }
    __syncthreads();
    float inv = inv_s;
    for (int d = t; d < D; d += 256) g_f[(size_t)r * D + d] = row[d] * inv;
}

// ---------------- per-batch bookkeeping: rank, group size, first index, scatter ----------------
__global__ void k_meta(const int* __restrict__ lab, const int* __restrict__ ptr) {
    __shared__ int sl[B];
    int i = threadIdx.x;
    sl[i] = lab[i];
    __syncthreads();
    int li = sl[i];
    int cb = 0, tot = 0, first = B;
    for (int j = 0; j < B; j++) {
        if (sl[j] == li) { tot++; if (j < i) cb++; if (j < first) first = j; }
    }
    g_rank[i] = cb; g_gsize[i] = tot; g_fidx[i] = first;
    int wp = (ptr[li] + cb) % M;
    if (wp < KP) atomicMax(&g_ov[li*KP + wp], i);
}

// ---------------- in-batch positive sums: masked f @ f^T ----------------
__global__ void k_batchpos(const int* __restrict__ lab) {
    int b = blockIdx.x, t = threadIdx.x;
    __shared__ float fb[D];
    for (int d = t; d < D; d += 256) fb[d] = g_f[(size_t)b*D + d];
    __syncthreads();
    int lb = lab[b], fi = g_fidx[b], gs = g_gsize[b];
    float s = 0.f; int c = 0;
    if (gs > 1) {
        for (int j = t; j < B; j += 256) {
            if (lab[j] == lb && g_rank[j] != fi) {
                const float* fj = g_f + (size_t)j * D;
                float d0 = 0.f;
                for (int d = 0; d < D; d++) d0 = fmaf(fb[d], fj[d], d0);
                s += d0 / TEMP; c++;
            }
        }
    }
    for (int o = 16; o; o >>= 1) {
        s += __shfl_down_sync(0xffffffffu, s, o);
        c += __shfl_down_sync(0xffffffffu, c, o);
    }
    __shared__ float ss[8]; __shared__ int cs[8];
    int lane = t & 31, w = t >> 5;
    if (!lane) { ss[w] = s; cs[w] = c; }
    __syncthreads();
    if (t == 0) {
        float S = 0.f; int CC = 0;
        for (int i = 0; i < 8; i++) { S += ss[i]; CC += cs[i]; }
        g_posb[b] = S; g_cntb[b] = CC;
    }
}

// ---------------- own-class memory positives: 50 dots per b ----------------
__global__ void k_own(const int* __restrict__ lab, const float* __restrict__ mb) {
    int b = blockIdx.x, t = threadIdx.x;
    int lane = t & 31, w = t >> 5;
    __shared__ float fb[D];
    for (int d = t; d < D; d += 256) fb[d] = g_f[(size_t)b*D + d];
    __syncthreads();
    int c = lab[b];
    float acc = 0.f;
    for (int k = w; k < KP; k += 8) {
        int o = g_ov[c*KP + k];
        const float* row = (o >= 0) ? (g_f + (size_t)o * D)
                                    : (mb + ((size_t)c * M + k) * D);
        float s = 0.f;
        for (int d = lane; d < D; d += 32) s = fmaf(fb[d], row[d], s);
        for (int off = 16; off; off >>= 1) s += __shfl_down_sync(0xffffffffu, s, off);
        if (!lane) acc += s / TEMP;
    }
    __shared__ float ws[8];
    if (!lane) ws[w] = acc;
    __syncthreads();
    if (t == 0) {
        float S = 0.f;
        for (int i = 0; i < 8; i++) S += ws[i];
        g_own[b] = S;
    }
}

// ---------------- main GEMM: sims over (b, c, k<20) with fused neg epilogue ----------------
__global__ __launch_bounds__(256) void k_gemm(const int* __restrict__ lab,
                                              const float* __restrict__ mb) {
    __shared__ float As[BK][BM];
    __shared__ float Bs[BK][BN];
    __shared__ const float* bptr[BN];
    __shared__ int ncls[BN];

    int ntile = blockIdx.x, btile = blockIdx.y;
    int n0 = ntile * BN, b0 = btile * BM;
    int tid = threadIdx.x;
    int tx = tid & 15, ty = tid >> 4;

    for (int i = tid; i < BN; i += 256) {
        int n = n0 + i;
        if (n < NROWS) {
            int c = n / KN, k = n - c * KN;
            int o = g_ov[c*KP + k];
            bptr[i] = (o >= 0) ? (g_f + (size_t)o * D)
                               : (mb + ((size_t)c * M + k) * D);
            ncls[i] = c;
        } else {
            bptr[i] = g_f;       // safe dummy; masked in epilogue
            ncls[i] = -1;
        }
    }
    __syncthreads();

    float acc[4][8];
    #pragma unroll
    for (int i = 0; i < 4; i++)
        #pragma unroll
        for (int j = 0; j < 8; j++) acc[i][j] = 0.f;

    int la_b = tid >> 2;            // 0..63
    int la_k = (tid & 3) * 4;       // 0,4,8,12
    int lb_n = tid >> 1;            // 0..127
    int lb_k = (tid & 1) * 8;       // 0 or 8
    const float* arow = g_f + (size_t)(b0 + la_b) * D + la_k;
    const float* brow = bptr[lb_n] + lb_k;

    for (int k0 = 0; k0 < D; k0 += BK) {
        float4 av  = *(const float4*)(arow + k0);
        float4 bv0 = *(const float4*)(brow + k0);
        float4 bv1 = *(const float4*)(brow + k0 + 4);
        As[la_k+0][la_b] = av.x;  As[la_k+1][la_b] = av.y;
        As[la_k+2][la_b] = av.z;  As[la_k+3][la_b] = av.w;
        Bs[lb_k+0][lb_n] = bv0.x; Bs[lb_k+1][lb_n] = bv0.y;
        Bs[lb_k+2][lb_n] = bv0.z; Bs[lb_k+3][lb_n] = bv0.w;
        Bs[lb_k+4][lb_n] = bv1.x; Bs[lb_k+5][lb_n] = bv1.y;
        Bs[lb_k+6][lb_n] = bv1.z; Bs[lb_k+7][lb_n] = bv1.w;
        __syncthreads();
        #pragma unroll
        for (int kk = 0; kk < BK; kk++) {
            float4 a  = *(const float4*)&As[kk][ty*4];
            float4 bA = *(const float4*)&Bs[kk][tx*8];
            float4 bB = *(const float4*)&Bs[kk][tx*8 + 4];
            float ar[4] = {a.x, a.y, a.z, a.w};
            float br[8] = {bA.x, bA.y, bA.z, bA.w, bB.x, bB.y, bB.z, bB.w};
            #pragma unroll
            for (int i = 0; i < 4; i++)
                #pragma unroll
                for (int j = 0; j < 8; j++)
                    acc[i][j] = fmaf(ar[i], br[j], acc[i][j]);
        }
        __syncthreads();
    }

    // epilogue: per-b hard/all sums over this n-tile, reduced across tx (width 16)
    int blab[4];
    #pragma unroll
    for (int i = 0; i < 4; i++) blab[i] = lab[b0 + ty*4 + i];

    #pragma unroll
    for (int i = 0; i < 4; i++) {
        float alls = 0.f, hards = 0.f; int hc = 0;
        #pragma unroll
        for (int j = 0; j < 8; j++) {
            int idx = tx*8 + j;
            int c = ncls[idx];
            if (c >= 0 && c != blab[i]) {
                float sim = acc[i][j] / TEMP;
                alls += sim;
                if (sim > MARGIN) { hards += sim; hc++; }
            }
        }
        for (int off = 8; off; off >>= 1) {
            alls  += __shfl_down_sync(0xffffffffu, alls,  off, 16);
            hards += __shfl_down_sync(0xffffffffu, hards, off, 16);
            hc    += __shfl_down_sync(0xffffffffu, hc,    off, 16);
        }
        if (tx == 0) {
            int gb = b0 + ty*4 + i;
            g_all [ntile*B + gb] = alls;
            g_hard[ntile*B + gb] = hards;
            g_hcnt[ntile*B + gb] = hc;
        }
    }
}

// ---------------- finalize: combine, per-b loss, mean ----------------
__global__ void k_final(float* __restrict__ out) {
    int b = threadIdx.x;
    float alls = 0.f, hards = 0.f; int hc = 0;
    for (int t = 0; t < NT; t++) {
        alls  += g_all [t*B + b];
        hards += g_hard[t*B + b];
        hc    += g_hcnt[t*B + b];
    }
    float pos_sum = g_posb[b] + g_own[b];
    float pos_cnt = (float)(g_cntb[b] + KP);
    float pos_loss = -pos_sum / pos_cnt;
    float neg_loss = (hc > 0) ? (hards / (float)(hc > 1 ? hc : 1))
                              : (alls / (float)((C-1) * KN));
    __shared__ float sm[B];
    sm[b] = pos_loss + neg_loss;
    __syncthreads();
    for (int s = 256; s; s >>= 1) {
        if (b < s) sm[b] += sm[b + s];
        __syncthreads();
    }
    if (b == 0) out[0] = sm[0] / (float)B;
}

// ---------------- launch ----------------
extern "C" void kernel_launch(void* const* d_in, const int* in_sizes, int n_in,
                              void* d_out, int out_size) {
    const float* features   = (const float*)d_in[0];
    const int*   labels     = (const int*)  d_in[1];
    const float* memorybank = (const float*)d_in[2];
    const int*   memoryptr  = (const int*)  d_in[3];
    float* out = (float*)d_out;

    k_init    <<<(C*KP + 255)/256, 256>>>();
    k_norm    <<<B, 256>>>(features);
    k_meta    <<<1, B>>>(labels, memoryptr);
    k_batchpos<<<B, 256>>>(labels);
    k_own     <<<B, 256>>>(labels, memorybank);
    k_gemm    <<<dim3(NT, B/BM), 256>>>(labels, memorybank);
    k_final   <<<1, B>>>(out);
}